// round 3
// baseline (speedup 1.0000x reference)
#include <cuda_runtime.h>
#include <math.h>

#define GRID_RES 256
#define CELLSZ   0.015f
#define NS       64
#define MIN_BETA 0.015f

__global__ void __launch_bounds__(256)
plainvoxels_render_kernel(
    const float* __restrict__ grid,        // [256,256,256,5]
    const float* __restrict__ beta,        // [1]
    const float* __restrict__ rays_o,      // [N,3]
    const float* __restrict__ rays_d,      // [N,3]
    const float* __restrict__ rays_d_norm, // [N,1]
    const float* __restrict__ nearp,       // [1]
    const float* __restrict__ farp,        // [1]
    float* __restrict__ out_rgb,     // [N,3]
    float* __restrict__ out_depth,   // [N,1]
    float* __restrict__ out_normals, // [N,3]
    float* __restrict__ out_acc,     // [N,1]
    float* __restrict__ out_grads,   // [N*NS,3]
    float* __restrict__ out_near,    // [N,1]
    float* __restrict__ out_far,     // [N,1]
    int N)
{
    const int warp_in_grid = (blockIdx.x * blockDim.x + threadIdx.x) >> 5;
    const int lane = threadIdx.x & 31;
    if (warp_in_grid >= N) return;
    const int n = warp_in_grid;

    // ORIGIN computed exactly as reference (fp32): -0.5*256*0.015
    const float ORIGIN = __fmul_rn(__fmul_rn(-0.5f, (float)GRID_RES), CELLSZ);

    const float ox = rays_o[3*n+0], oy = rays_o[3*n+1], oz = rays_o[3*n+2];
    const float dx = rays_d[3*n+0], dy = rays_d[3*n+1], dz = rays_d[3*n+2];
    const float nr = nearp[0], fr = farp[0];
    const float dt = __fdiv_rn(__fsub_rn(fr, nr), (float)NS);
    const float beta_eff = MIN_BETA + fabsf(beta[0]);
    const float inv_beta = 1.0f / beta_eff;
    const float inv_cell = 1.0f / CELLSZ;

    float tau_h[2], rgb_h[2][3], nml_h[2][3], tm_h[2];

    #pragma unroll
    for (int h = 0; h < 2; h++) {
        const int s = lane + 32 * h;
        // exact reference rounding: t_n = near + i*dt; t_f = t_n + dt; t_mid = 0.5*(t_n+t_f)
        const float t_n  = __fadd_rn(nr, __fmul_rn((float)s, dt));
        const float t_f  = __fadd_rn(t_n, dt);
        const float t_mid = __fmul_rn(0.5f, __fadd_rn(t_n, t_f));
        tm_h[h] = t_mid;
        // exact reference rounding: x = o + t_mid * d (mul then add, no fma)
        const float px = __fadd_rn(ox, __fmul_rn(t_mid, dx));
        const float py = __fadd_rn(oy, __fmul_rn(t_mid, dy));
        const float pz = __fadd_rn(oz, __fmul_rn(t_mid, dz));

        // exact reference rounding: u = (x - ORIGIN) / CELL (true division)
        const float ux = __fdiv_rn(__fsub_rn(px, ORIGIN), CELLSZ);
        const float uy = __fdiv_rn(__fsub_rn(py, ORIGIN), CELLSZ);
        const float uz = __fdiv_rn(__fsub_rn(pz, ORIGIN), CELLSZ);

        const bool mask = (ux >= 0.0f) && (ux <= (float)(GRID_RES-1)) &&
                          (uy >= 0.0f) && (uy <= (float)(GRID_RES-1)) &&
                          (uz >= 0.0f) && (uz <= (float)(GRID_RES-1));

        int ix = min(max((int)floorf(ux), 0), GRID_RES - 2);
        int iy = min(max((int)floorf(uy), 0), GRID_RES - 2);
        int iz = min(max((int)floorf(uz), 0), GRID_RES - 2);
        const float fx = __fsub_rn(ux, (float)ix);
        const float fy = __fsub_rn(uy, (float)iy);
        const float fz = __fsub_rn(uz, (float)iz);

        const long long base = ((((long long)ix * GRID_RES + iy) * GRID_RES) + iz) * 5;
        const long long OX = (long long)GRID_RES * GRID_RES * 5;
        const long long OY = (long long)GRID_RES * 5;
        const long long OZ = 5;

        // load 8 corners x 4 channels (sdf, r, g, b); bit2=dx, bit1=dy, bit0=dz
        float v[8][4];
        #pragma unroll
        for (int c = 0; c < 8; c++) {
            const long long off = base + ((c & 4) ? OX : 0)
                                       + ((c & 2) ? OY : 0)
                                       + ((c & 1) ? OZ : 0);
            const float* p = grid + off;
            v[c][0] = __ldg(p + 0);
            v[c][1] = __ldg(p + 1);
            v[c][2] = __ldg(p + 2);
            v[c][3] = __ldg(p + 3);
        }
        const float gx = 1.0f - fx, gy = 1.0f - fy, gz = 1.0f - fz;

        float feat[4];
        #pragma unroll
        for (int ch = 0; ch < 4; ch++) {
            const float c00 = v[0][ch] * gx + v[4][ch] * fx;
            const float c10 = v[2][ch] * gx + v[6][ch] * fx;
            const float c01 = v[1][ch] * gx + v[5][ch] * fx;
            const float c11 = v[3][ch] * gx + v[7][ch] * fx;
            const float c0 = c00 * gy + c10 * fy;
            const float c1 = c01 * gy + c11 * fy;
            feat[ch] = c0 * gz + c1 * fz;
        }
        const float sdf = feat[0];
        rgb_h[h][0] = feat[1]; rgb_h[h][1] = feat[2]; rgb_h[h][2] = feat[3];

        // analytic gradient of trilinear sdf (indices constant under grad)
        const float dfx = ((v[4][0]-v[0][0])*gy + (v[6][0]-v[2][0])*fy) * gz
                        + ((v[5][0]-v[1][0])*gy + (v[7][0]-v[3][0])*fy) * fz;
        const float dfy = ((v[2][0]-v[0][0])*gx + (v[6][0]-v[4][0])*fx) * gz
                        + ((v[3][0]-v[1][0])*gx + (v[7][0]-v[5][0])*fx) * fz;
        const float dfz = ((v[1][0]-v[0][0])*gx + (v[5][0]-v[4][0])*fx) * gy
                        + ((v[3][0]-v[2][0])*gx + (v[7][0]-v[6][0])*fx) * fy;
        const float grx = __fdiv_rn(dfx, CELLSZ);
        const float gry = __fdiv_rn(dfy, CELLSZ);
        const float grz = __fdiv_rn(dfz, CELLSZ);

        const long long m = (long long)n * NS + s;
        out_grads[3*m+0] = grx;
        out_grads[3*m+1] = gry;
        out_grads[3*m+2] = grz;

        // unit normals — IEEE sqrt/div to match reference precision
        const float gl = __fsqrt_rn(__fadd_rn(__fadd_rn(__fmul_rn(grx,grx), __fmul_rn(gry,gry)), __fmul_rn(grz,grz)));
        const float den = fmaxf(gl, 1e-12f);
        nml_h[h][0] = __fdiv_rn(grx, den);
        nml_h[h][1] = __fdiv_rn(gry, den);
        nml_h[h][2] = __fdiv_rn(grz, den);

        // Laplace CDF density
        const float sgn = (sdf > 0.0f) ? 1.0f : ((sdf < 0.0f) ? -1.0f : 0.0f);
        float sigma = inv_beta * (0.5f + 0.5f * sgn * expm1f(-fabsf(sdf) * inv_beta));
        if (!mask) sigma = 0.0f;
        tau_h[h] = sigma * dt;
    }

    // ---- exclusive prefix of tau over 64 samples ----
    float x0 = tau_h[0];
    #pragma unroll
    for (int o = 1; o < 32; o <<= 1) {
        float y = __shfl_up_sync(0xFFFFFFFFu, x0, o);
        if (lane >= o) x0 += y;
    }
    const float total0 = __shfl_sync(0xFFFFFFFFu, x0, 31);
    float x1 = tau_h[1];
    #pragma unroll
    for (int o = 1; o < 32; o <<= 1) {
        float y = __shfl_up_sync(0xFFFFFFFFu, x1, o);
        if (lane >= o) x1 += y;
    }
    const float excl0 = x0 - tau_h[0];
    const float excl1 = total0 + x1 - tau_h[1];

    const float T0 = expf(-excl0);
    const float T1 = expf(-excl1);
    const float a0 = -expm1f(-tau_h[0]);
    const float a1 = -expm1f(-tau_h[1]);
    const float w0 = T0 * a0;
    const float w1 = T1 * a1;

    float acc_r = w0 * rgb_h[0][0] + w1 * rgb_h[1][0];
    float acc_g = w0 * rgb_h[0][1] + w1 * rgb_h[1][1];
    float acc_b = w0 * rgb_h[0][2] + w1 * rgb_h[1][2];
    float acc_nx = w0 * nml_h[0][0] + w1 * nml_h[1][0];
    float acc_ny = w0 * nml_h[0][1] + w1 * nml_h[1][1];
    float acc_nz = w0 * nml_h[0][2] + w1 * nml_h[1][2];
    float acc_d  = w0 * tm_h[0] + w1 * tm_h[1];
    float acc_w  = w0 + w1;

    #pragma unroll
    for (int o = 16; o >= 1; o >>= 1) {
        acc_r  += __shfl_xor_sync(0xFFFFFFFFu, acc_r,  o);
        acc_g  += __shfl_xor_sync(0xFFFFFFFFu, acc_g,  o);
        acc_b  += __shfl_xor_sync(0xFFFFFFFFu, acc_b,  o);
        acc_nx += __shfl_xor_sync(0xFFFFFFFFu, acc_nx, o);
        acc_ny += __shfl_xor_sync(0xFFFFFFFFu, acc_ny, o);
        acc_nz += __shfl_xor_sync(0xFFFFFFFFu, acc_nz, o);
        acc_d  += __shfl_xor_sync(0xFFFFFFFFu, acc_d,  o);
        acc_w  += __shfl_xor_sync(0xFFFFFFFFu, acc_w,  o);
    }

    if (lane == 0) {
        const float inv_rdn = __fdiv_rn(1.0f, rays_d_norm[n]);
        out_rgb[3*n+0] = acc_r;
        out_rgb[3*n+1] = acc_g;
        out_rgb[3*n+2] = acc_b;
        out_depth[n]   = __fdiv_rn(acc_d, rays_d_norm[n]);
        out_normals[3*n+0] = acc_nx;
        out_normals[3*n+1] = acc_ny;
        out_normals[3*n+2] = acc_nz;
        out_acc[n]     = acc_w;
        out_near[n]    = __fdiv_rn(nr, rays_d_norm[n]);
        out_far[n]     = __fdiv_rn(fr, rays_d_norm[n]);
        (void)inv_rdn;
    }
}

extern "C" void kernel_launch(void* const* d_in, const int* in_sizes, int n_in,
                              void* d_out, int out_size) {
    const float* grid        = (const float*)d_in[0];
    const float* beta        = (const float*)d_in[1];
    const float* rays_o      = (const float*)d_in[2];
    const float* rays_d      = (const float*)d_in[3];
    const float* rays_d_norm = (const float*)d_in[4];
    const float* nearp       = (const float*)d_in[5];
    const float* farp        = (const float*)d_in[6];

    const int N = in_sizes[2] / 3;

    float* out = (float*)d_out;
    float* out_rgb     = out;                        // N*3
    float* out_depth   = out_rgb + (size_t)3 * N;    // N
    float* out_normals = out_depth + N;              // N*3
    float* out_acc     = out_normals + (size_t)3*N;  // N
    float* out_grads   = out_acc + N;                // N*NS*3
    float* out_near    = out_grads + (size_t)3 * N * NS; // N
    float* out_far     = out_near + N;               // N

    const int threads = 256;
    const int blocks  = (N * 32 + threads - 1) / threads;
    plainvoxels_render_kernel<<<blocks, threads>>>(
        grid, beta, rays_o, rays_d, rays_d_norm, nearp, farp,
        out_rgb, out_depth, out_normals, out_acc, out_grads, out_near, out_far, N);
}

// round 5
// speedup vs baseline: 1.1363x; 1.1363x over previous
#include <cuda_runtime.h>
#include <math.h>

#define GRID_RES 256
#define CELLSZ   0.015f
#define NS       64
#define MIN_BETA 0.015f

// 128 threads = 4 warps = 2 rays per block; thread-per-sample.
__global__ void __launch_bounds__(128)
plainvoxels_render_kernel(
    const float* __restrict__ grid,        // [256,256,256,5]
    const float* __restrict__ beta,        // [1]
    const float* __restrict__ rays_o,      // [N,3]
    const float* __restrict__ rays_d,      // [N,3]
    const float* __restrict__ rays_d_norm, // [N,1]
    const float* __restrict__ nearp,       // [1]
    const float* __restrict__ farp,        // [1]
    float* __restrict__ out_rgb,     // [N,3]
    float* __restrict__ out_depth,   // [N,1]
    float* __restrict__ out_normals, // [N,3]
    float* __restrict__ out_acc,     // [N,1]
    float* __restrict__ out_grads,   // [N*NS,3]
    float* __restrict__ out_near,    // [N,1]
    float* __restrict__ out_far,     // [N,1]
    int N)
{
    __shared__ float warp_tot[4];     // per-warp tau totals
    __shared__ float red[4][8];       // per-warp reduced accumulators

    const int tid  = threadIdx.x;
    const int warp = tid >> 5;
    const int lane = tid & 31;
    const int s    = tid & 63;                    // sample index within ray
    const int nray = blockIdx.x * 2 + (tid >> 6); // global ray id
    const bool valid = (nray < N);
    const int n = valid ? nray : (N - 1);         // clamp; invalid threads still sync

    const float ORIGIN = __fmul_rn(__fmul_rn(-0.5f, (float)GRID_RES), CELLSZ);

    const float ox = rays_o[3*n+0], oy = rays_o[3*n+1], oz = rays_o[3*n+2];
    const float dx = rays_d[3*n+0], dy = rays_d[3*n+1], dz = rays_d[3*n+2];
    const float nr = nearp[0], fr = farp[0];
    const float dt = __fdiv_rn(__fsub_rn(fr, nr), (float)NS);
    const float beta_eff = MIN_BETA + fabsf(beta[0]);
    const float inv_beta = 1.0f / beta_eff;

    // exact reference rounding for sample position
    const float t_n   = __fadd_rn(nr, __fmul_rn((float)s, dt));
    const float t_f   = __fadd_rn(t_n, dt);
    const float t_mid = __fmul_rn(0.5f, __fadd_rn(t_n, t_f));
    const float px = __fadd_rn(ox, __fmul_rn(t_mid, dx));
    const float py = __fadd_rn(oy, __fmul_rn(t_mid, dy));
    const float pz = __fadd_rn(oz, __fmul_rn(t_mid, dz));

    const float ux = __fdiv_rn(__fsub_rn(px, ORIGIN), CELLSZ);
    const float uy = __fdiv_rn(__fsub_rn(py, ORIGIN), CELLSZ);
    const float uz = __fdiv_rn(__fsub_rn(pz, ORIGIN), CELLSZ);

    const bool mask = (ux >= 0.0f) && (ux <= (float)(GRID_RES-1)) &&
                      (uy >= 0.0f) && (uy <= (float)(GRID_RES-1)) &&
                      (uz >= 0.0f) && (uz <= (float)(GRID_RES-1));

    const int ix = min(max((int)floorf(ux), 0), GRID_RES - 2);
    const int iy = min(max((int)floorf(uy), 0), GRID_RES - 2);
    const int iz = min(max((int)floorf(uz), 0), GRID_RES - 2);
    const float fx = __fsub_rn(ux, (float)ix);
    const float fy = __fsub_rn(uy, (float)iy);
    const float fz = __fsub_rn(uz, (float)iz);

    const long long base = ((((long long)ix * GRID_RES + iy) * GRID_RES) + iz) * 5;
    const long long OX = (long long)GRID_RES * GRID_RES * 5;
    const long long OY = (long long)GRID_RES * 5;
    const long long OZ = 5;

    // 8 corners x 4 channels; bit2=dx, bit1=dy, bit0=dz — batch all 32 loads
    float v[8][4];
    #pragma unroll
    for (int c = 0; c < 8; c++) {
        const long long off = base + ((c & 4) ? OX : 0)
                                   + ((c & 2) ? OY : 0)
                                   + ((c & 1) ? OZ : 0);
        const float* p = grid + off;
        v[c][0] = __ldg(p + 0);
        v[c][1] = __ldg(p + 1);
        v[c][2] = __ldg(p + 2);
        v[c][3] = __ldg(p + 3);
    }
    const float gx = 1.0f - fx, gy = 1.0f - fy, gz = 1.0f - fz;

    float feat[4];
    #pragma unroll
    for (int ch = 0; ch < 4; ch++) {
        const float c00 = v[0][ch] * gx + v[4][ch] * fx;
        const float c10 = v[2][ch] * gx + v[6][ch] * fx;
        const float c01 = v[1][ch] * gx + v[5][ch] * fx;
        const float c11 = v[3][ch] * gx + v[7][ch] * fx;
        const float c0 = c00 * gy + c10 * fy;
        const float c1 = c01 * gy + c11 * fy;
        feat[ch] = c0 * gz + c1 * fz;
    }
    const float sdf = feat[0];

    // analytic gradient of trilinear sdf
    const float dfx = ((v[4][0]-v[0][0])*gy + (v[6][0]-v[2][0])*fy) * gz
                    + ((v[5][0]-v[1][0])*gy + (v[7][0]-v[3][0])*fy) * fz;
    const float dfy = ((v[2][0]-v[0][0])*gx + (v[6][0]-v[4][0])*fx) * gz
                    + ((v[3][0]-v[1][0])*gx + (v[7][0]-v[5][0])*fx) * fz;
    const float dfz = ((v[1][0]-v[0][0])*gx + (v[5][0]-v[4][0])*fx) * gy
                    + ((v[3][0]-v[2][0])*gx + (v[7][0]-v[6][0])*fx) * fy;
    const float grx = __fdiv_rn(dfx, CELLSZ);
    const float gry = __fdiv_rn(dfy, CELLSZ);
    const float grz = __fdiv_rn(dfz, CELLSZ);

    if (valid) {
        const long long m = (long long)n * NS + s;
        out_grads[3*m+0] = grx;
        out_grads[3*m+1] = gry;
        out_grads[3*m+2] = grz;
    }

    // unit normal (IEEE ops to match reference rounding)
    const float gl = __fsqrt_rn(__fadd_rn(__fadd_rn(__fmul_rn(grx,grx),
                        __fmul_rn(gry,gry)), __fmul_rn(grz,grz)));
    const float den = fmaxf(gl, 1e-12f);
    const float nx = __fdiv_rn(grx, den);
    const float ny = __fdiv_rn(gry, den);
    const float nz = __fdiv_rn(grz, den);

    // Laplace CDF density
    const float sgn = (sdf > 0.0f) ? 1.0f : ((sdf < 0.0f) ? -1.0f : 0.0f);
    float sigma = inv_beta * (0.5f + 0.5f * sgn * expm1f(-fabsf(sdf) * inv_beta));
    if (!mask) sigma = 0.0f;
    const float tau = sigma * dt;

    // ---- 2-warp exclusive prefix of tau over 64 samples ----
    float x = tau;
    #pragma unroll
    for (int o = 1; o < 32; o <<= 1) {
        float y = __shfl_up_sync(0xFFFFFFFFu, x, o);
        if (lane >= o) x += y;
    }
    if (lane == 31) warp_tot[warp] = x;
    __syncthreads();
    float excl = x - tau;
    if (s >= 32) excl += warp_tot[warp - 1];  // add lower-half total of same ray

    const float T = expf(-excl);
    const float a = -expm1f(-tau);
    const float w = T * a;

    // ---- composite: 8 accumulators, warp reduce then combine pairs ----
    float acc[8];
    acc[0] = w * feat[1];
    acc[1] = w * feat[2];
    acc[2] = w * feat[3];
    acc[3] = w * nx;
    acc[4] = w * ny;
    acc[5] = w * nz;
    acc[6] = w * t_mid;
    acc[7] = w;

    #pragma unroll
    for (int o = 16; o >= 1; o >>= 1) {
        #pragma unroll
        for (int k = 0; k < 8; k++)
            acc[k] += __shfl_xor_sync(0xFFFFFFFFu, acc[k], o);
    }
    if (lane == 0) {
        #pragma unroll
        for (int k = 0; k < 8; k++) red[warp][k] = acc[k];
    }
    __syncthreads();

    if ((tid & 63) == 0 && valid) {   // lane 0 of even warp: owns ray output
        float r0 = red[warp][0] + red[warp+1][0];
        float r1 = red[warp][1] + red[warp+1][1];
        float r2 = red[warp][2] + red[warp+1][2];
        float r3 = red[warp][3] + red[warp+1][3];
        float r4 = red[warp][4] + red[warp+1][4];
        float r5 = red[warp][5] + red[warp+1][5];
        float r6 = red[warp][6] + red[warp+1][6];
        float r7 = red[warp][7] + red[warp+1][7];
        const float rdn = rays_d_norm[n];
        out_rgb[3*n+0] = r0;
        out_rgb[3*n+1] = r1;
        out_rgb[3*n+2] = r2;
        out_depth[n]   = __fdiv_rn(r6, rdn);
        out_normals[3*n+0] = r3;
        out_normals[3*n+1] = r4;
        out_normals[3*n+2] = r5;
        out_acc[n]     = r7;
        out_near[n]    = __fdiv_rn(nr, rdn);
        out_far[n]     = __fdiv_rn(fr, rdn);
    }
}

extern "C" void kernel_launch(void* const* d_in, const int* in_sizes, int n_in,
                              void* d_out, int out_size) {
    const float* grid        = (const float*)d_in[0];
    const float* beta        = (const float*)d_in[1];
    const float* rays_o      = (const float*)d_in[2];
    const float* rays_d      = (const float*)d_in[3];
    const float* rays_d_norm = (const float*)d_in[4];
    const float* nearp       = (const float*)d_in[5];
    const float* farp        = (const float*)d_in[6];

    const int N = in_sizes[2] / 3;

    float* out = (float*)d_out;
    float* out_rgb     = out;                        // N*3
    float* out_depth   = out_rgb + (size_t)3 * N;    // N
    float* out_normals = out_depth + N;              // N*3
    float* out_acc     = out_normals + (size_t)3*N;  // N
    float* out_grads   = out_acc + N;                // N*NS*3
    float* out_near    = out_grads + (size_t)3 * N * NS; // N
    float* out_far     = out_near + N;               // N

    const int threads = 128;                  // 2 rays per block
    const int blocks  = (N * NS + threads - 1) / threads;
    plainvoxels_render_kernel<<<blocks, threads>>>(
        grid, beta, rays_o, rays_d, rays_d_norm, nearp, farp,
        out_rgb, out_depth, out_normals, out_acc, out_grads, out_near, out_far, N);
}

// round 6
// speedup vs baseline: 1.5424x; 1.3574x over previous
#include <cuda_runtime.h>
#include <math.h>

#define GRID_RES 256
#define CELLSZ   0.015f
#define NS       64
#define MIN_BETA 0.015f

// 128 threads = 4 warps = 2 rays per block; thread-per-sample.
// min 8 blocks/SM -> ~64 reg budget so the 32 gathers can be front-batched (high MLP).
__global__ void __launch_bounds__(128, 8)
plainvoxels_render_kernel(
    const float* __restrict__ grid,        // [256,256,256,5]
    const float* __restrict__ beta,        // [1]
    const float* __restrict__ rays_o,      // [N,3]
    const float* __restrict__ rays_d,      // [N,3]
    const float* __restrict__ rays_d_norm, // [N,1]
    const float* __restrict__ nearp,       // [1]
    const float* __restrict__ farp,        // [1]
    float* __restrict__ out_rgb,     // [N,3]
    float* __restrict__ out_depth,   // [N,1]
    float* __restrict__ out_normals, // [N,3]
    float* __restrict__ out_acc,     // [N,1]
    float* __restrict__ out_grads,   // [N*NS,3]
    float* __restrict__ out_near,    // [N,1]
    float* __restrict__ out_far,     // [N,1]
    int N)
{
    __shared__ float warp_tot[4];     // per-warp tau totals
    __shared__ float red[4][8];       // per-warp reduced accumulators

    const int tid  = threadIdx.x;
    const int warp = tid >> 5;
    const int lane = tid & 31;
    const int s    = tid & 63;                    // sample index within ray
    const int nray = blockIdx.x * 2 + (tid >> 6); // global ray id
    const bool valid = (nray < N);
    const int n = valid ? nray : (N - 1);         // clamp; invalid threads still sync

    const float ORIGIN = __fmul_rn(__fmul_rn(-0.5f, (float)GRID_RES), CELLSZ);

    const float ox = rays_o[3*n+0], oy = rays_o[3*n+1], oz = rays_o[3*n+2];
    const float dx = rays_d[3*n+0], dy = rays_d[3*n+1], dz = rays_d[3*n+2];
    const float nr = nearp[0], fr = farp[0];
    const float dt = __fdiv_rn(__fsub_rn(fr, nr), (float)NS);
    const float beta_eff = MIN_BETA + fabsf(beta[0]);
    const float inv_beta = 1.0f / beta_eff;

    // exact reference rounding for sample position
    const float t_n   = __fadd_rn(nr, __fmul_rn((float)s, dt));
    const float t_f   = __fadd_rn(t_n, dt);
    const float t_mid = __fmul_rn(0.5f, __fadd_rn(t_n, t_f));
    const float px = __fadd_rn(ox, __fmul_rn(t_mid, dx));
    const float py = __fadd_rn(oy, __fmul_rn(t_mid, dy));
    const float pz = __fadd_rn(oz, __fmul_rn(t_mid, dz));

    const float ux = __fdiv_rn(__fsub_rn(px, ORIGIN), CELLSZ);
    const float uy = __fdiv_rn(__fsub_rn(py, ORIGIN), CELLSZ);
    const float uz = __fdiv_rn(__fsub_rn(pz, ORIGIN), CELLSZ);

    const bool mask = (ux >= 0.0f) && (ux <= (float)(GRID_RES-1)) &&
                      (uy >= 0.0f) && (uy <= (float)(GRID_RES-1)) &&
                      (uz >= 0.0f) && (uz <= (float)(GRID_RES-1));

    const int ix = min(max((int)floorf(ux), 0), GRID_RES - 2);
    const int iy = min(max((int)floorf(uy), 0), GRID_RES - 2);
    const int iz = min(max((int)floorf(uz), 0), GRID_RES - 2);
    const float fx = __fsub_rn(ux, (float)ix);
    const float fy = __fsub_rn(uy, (float)iy);
    const float fz = __fsub_rn(uz, (float)iz);

    // 32-bit index math: max index 256^3*5 < 2^31
    const int base = ((ix * GRID_RES + iy) * GRID_RES + iz) * 5;
    const int OX = GRID_RES * GRID_RES * 5;
    const int OY = GRID_RES * 5;

    // four z-pair base pointers (each pair: corner dz=0 at p[0..3], dz=1 at p[5..8])
    const float* p00 = grid + base;            // dx=0, dy=0
    const float* p01 = grid + base + OY;       // dx=0, dy=1
    const float* p10 = grid + base + OX;       // dx=1, dy=0
    const float* p11 = grid + base + OX + OY;  // dx=1, dy=1

    // Front-batch ALL 32 loads into a flat register array before any FP use.
    // v[c][ch], corner bit2=dx, bit1=dy, bit0=dz
    float v[8][4];
    #pragma unroll
    for (int ch = 0; ch < 4; ch++) v[0][ch] = __ldg(p00 + ch);
    #pragma unroll
    for (int ch = 0; ch < 4; ch++) v[1][ch] = __ldg(p00 + 5 + ch);
    #pragma unroll
    for (int ch = 0; ch < 4; ch++) v[2][ch] = __ldg(p01 + ch);
    #pragma unroll
    for (int ch = 0; ch < 4; ch++) v[3][ch] = __ldg(p01 + 5 + ch);
    #pragma unroll
    for (int ch = 0; ch < 4; ch++) v[4][ch] = __ldg(p10 + ch);
    #pragma unroll
    for (int ch = 0; ch < 4; ch++) v[5][ch] = __ldg(p10 + 5 + ch);
    #pragma unroll
    for (int ch = 0; ch < 4; ch++) v[6][ch] = __ldg(p11 + ch);
    #pragma unroll
    for (int ch = 0; ch < 4; ch++) v[7][ch] = __ldg(p11 + 5 + ch);

    const float gx = 1.0f - fx, gy = 1.0f - fy, gz = 1.0f - fz;

    float feat[4];
    #pragma unroll
    for (int ch = 0; ch < 4; ch++) {
        const float c00 = v[0][ch] * gx + v[4][ch] * fx;
        const float c10 = v[2][ch] * gx + v[6][ch] * fx;
        const float c01 = v[1][ch] * gx + v[5][ch] * fx;
        const float c11 = v[3][ch] * gx + v[7][ch] * fx;
        const float c0 = c00 * gy + c10 * fy;
        const float c1 = c01 * gy + c11 * fy;
        feat[ch] = c0 * gz + c1 * fz;
    }
    const float sdf = feat[0];

    // analytic gradient of trilinear sdf
    const float dfx = ((v[4][0]-v[0][0])*gy + (v[6][0]-v[2][0])*fy) * gz
                    + ((v[5][0]-v[1][0])*gy + (v[7][0]-v[3][0])*fy) * fz;
    const float dfy = ((v[2][0]-v[0][0])*gx + (v[6][0]-v[4][0])*fx) * gz
                    + ((v[3][0]-v[1][0])*gx + (v[7][0]-v[5][0])*fx) * fz;
    const float dfz = ((v[1][0]-v[0][0])*gx + (v[5][0]-v[4][0])*fx) * gy
                    + ((v[3][0]-v[2][0])*gx + (v[7][0]-v[6][0])*fx) * fy;
    const float grx = __fdiv_rn(dfx, CELLSZ);
    const float gry = __fdiv_rn(dfy, CELLSZ);
    const float grz = __fdiv_rn(dfz, CELLSZ);

    if (valid) {
        const int m = n * NS + s;
        out_grads[3*m+0] = grx;
        out_grads[3*m+1] = gry;
        out_grads[3*m+2] = grz;
    }

    // unit normal (IEEE ops to match reference rounding)
    const float gl = __fsqrt_rn(__fadd_rn(__fadd_rn(__fmul_rn(grx,grx),
                        __fmul_rn(gry,gry)), __fmul_rn(grz,grz)));
    const float den = fmaxf(gl, 1e-12f);
    const float nx = __fdiv_rn(grx, den);
    const float ny = __fdiv_rn(gry, den);
    const float nz = __fdiv_rn(grz, den);

    // Laplace CDF density
    const float sgn = (sdf > 0.0f) ? 1.0f : ((sdf < 0.0f) ? -1.0f : 0.0f);
    float sigma = inv_beta * (0.5f + 0.5f * sgn * expm1f(-fabsf(sdf) * inv_beta));
    if (!mask) sigma = 0.0f;
    const float tau = sigma * dt;

    // ---- 2-warp exclusive prefix of tau over 64 samples ----
    float x = tau;
    #pragma unroll
    for (int o = 1; o < 32; o <<= 1) {
        float y = __shfl_up_sync(0xFFFFFFFFu, x, o);
        if (lane >= o) x += y;
    }
    if (lane == 31) warp_tot[warp] = x;
    __syncthreads();
    float excl = x - tau;
    if (s >= 32) excl += warp_tot[warp - 1];  // add lower-half total of same ray

    const float T = expf(-excl);
    const float a = -expm1f(-tau);
    const float w = T * a;

    // ---- composite: 8 accumulators, warp reduce then combine pairs ----
    float acc[8];
    acc[0] = w * feat[1];
    acc[1] = w * feat[2];
    acc[2] = w * feat[3];
    acc[3] = w * nx;
    acc[4] = w * ny;
    acc[5] = w * nz;
    acc[6] = w * t_mid;
    acc[7] = w;

    #pragma unroll
    for (int o = 16; o >= 1; o >>= 1) {
        #pragma unroll
        for (int k = 0; k < 8; k++)
            acc[k] += __shfl_xor_sync(0xFFFFFFFFu, acc[k], o);
    }
    if (lane == 0) {
        #pragma unroll
        for (int k = 0; k < 8; k++) red[warp][k] = acc[k];
    }
    __syncthreads();

    if ((tid & 63) == 0 && valid) {   // lane 0 of even warp: owns ray output
        float r0 = red[warp][0] + red[warp+1][0];
        float r1 = red[warp][1] + red[warp+1][1];
        float r2 = red[warp][2] + red[warp+1][2];
        float r3 = red[warp][3] + red[warp+1][3];
        float r4 = red[warp][4] + red[warp+1][4];
        float r5 = red[warp][5] + red[warp+1][5];
        float r6 = red[warp][6] + red[warp+1][6];
        float r7 = red[warp][7] + red[warp+1][7];
        const float rdn = rays_d_norm[n];
        out_rgb[3*n+0] = r0;
        out_rgb[3*n+1] = r1;
        out_rgb[3*n+2] = r2;
        out_depth[n]   = __fdiv_rn(r6, rdn);
        out_normals[3*n+0] = r3;
        out_normals[3*n+1] = r4;
        out_normals[3*n+2] = r5;
        out_acc[n]     = r7;
        out_near[n]    = __fdiv_rn(nr, rdn);
        out_far[n]     = __fdiv_rn(fr, rdn);
    }
}

extern "C" void kernel_launch(void* const* d_in, const int* in_sizes, int n_in,
                              void* d_out, int out_size) {
    const float* grid        = (const float*)d_in[0];
    const float* beta        = (const float*)d_in[1];
    const float* rays_o      = (const float*)d_in[2];
    const float* rays_d      = (const float*)d_in[3];
    const float* rays_d_norm = (const float*)d_in[4];
    const float* nearp       = (const float*)d_in[5];
    const float* farp        = (const float*)d_in[6];

    const int N = in_sizes[2] / 3;

    float* out = (float*)d_out;
    float* out_rgb     = out;                        // N*3
    float* out_depth   = out_rgb + (size_t)3 * N;    // N
    float* out_normals = out_depth + N;              // N*3
    float* out_acc     = out_normals + (size_t)3*N;  // N
    float* out_grads   = out_acc + N;                // N*NS*3
    float* out_near    = out_grads + (size_t)3 * N * NS; // N
    float* out_far     = out_near + N;               // N

    const int threads = 128;                  // 2 rays per block
    const int blocks  = (N * NS + threads - 1) / threads;
    plainvoxels_render_kernel<<<blocks, threads>>>(
        grid, beta, rays_o, rays_d, rays_d_norm, nearp, farp,
        out_rgb, out_depth, out_normals, out_acc, out_grads, out_near, out_far, N);
}